// round 10
// baseline (speedup 1.0000x reference)
#include <cuda_runtime.h>

// ---------------------------------------------------------------------------
// BottomUpHTMM — complete 4-ary tree depth 7, single persistent kernel.
// 128 blocks x 1024 threads (8 groups of 128 = (g,c)); each block owns two
// level-4 subtrees. a_sp / a_sp*log(a) tables live in SHARED memory (keeps
// regs <= 64 so 32 warps/SM). Redundant top per block; flag-based sync.
// ---------------------------------------------------------------------------

#define GC    128
#define NBLK  128

// tables (global)
__device__ float g_asp [4096];      // a_sp[g][i][l][j]   (wt=g*8+i -> wt*32+l*8+j)
__device__ float g_loga[4096];      // log sm_a
__device__ float g_bt  [16*256*8];  // sm_b[g][m][c]
__device__ float g_lbt [16*256*8];
__device__ float g_pit [512];       // sm_pi[g][pos][c]
__device__ float g_lpit[512];
__device__ float g_lsp [64];        // log sm_sp[g][l]

// leaf contribution tables: index (l*256+lab)*128 + wt
__device__ float g_uptab[1024 * GC];
__device__ float g_dntab[1024 * GC];

// cross-block state
__device__ float g_beta4 [256 * GC];
__device__ float g_beta3 [64 * GC];
__device__ float g_sbeta3[64 * GC];
__device__ float g_accum [16];

// sync state
__device__ unsigned g_cnt = 0;
__device__ unsigned g_gen = 0;
__device__ unsigned g_f1[NBLK];
__device__ unsigned g_c2;
__device__ unsigned g_cdn;
__device__ unsigned g_cfin;

// shared-memory layout (floats)
#define OFF_ASP   0        // 4096: a_sp copy
#define OFF_ALA   4096     // 4096: a_sp*log(a) copy
#define OFF_B6    8192     // 32 rows
#define OFF_S6    12288    // 32 rows
#define OFF_B5    16384    // 8 rows
#define OFF_S5    17408    // 8 rows
#define OFF_S4    18432    // 2 rows
#define OFF_E5    18688    // 8 rows
#define OFF_E6    19712    // 32 rows
#define OFF_TOP   23808    // 64 rows beta3 copy
#define OFF_B2    32000    // 16 rows
#define OFF_S2    34048    // 16 rows
#define OFF_B1    36096    // 4 rows
#define OFF_S1    36608    // 4 rows
#define OFF_E1    37120    // 4 rows
#define OFF_E2    37632    // 16 rows
#define OFF_E3    39680    // 1 row
#define OFF_E4    39808    // 2 rows
#define OFF_RED   40064    // 128
#define OFF_LAB   40192    // 208 ints
#define OFF_LAST  40400    // 1
#define SMEM_FLOATS 40404  // ~158 KB

__device__ __forceinline__ float sum8(float v) {
    v += __shfl_xor_sync(0xffffffffu, v, 4);
    v += __shfl_xor_sync(0xffffffffu, v, 2);
    v += __shfl_xor_sync(0xffffffffu, v, 1);
    return v;
}

// ---- acquire/release helpers ----
__device__ __forceinline__ void st_release(unsigned* p, unsigned v) {
    asm volatile("st.release.gpu.global.u32 [%0], %1;" :: "l"(p), "r"(v) : "memory");
}
__device__ __forceinline__ unsigned ld_acquire(unsigned* p) {
    unsigned v;
    asm volatile("ld.acquire.gpu.global.u32 %0, [%1];" : "=r"(v) : "l"(p) : "memory");
    return v;
}
__device__ __forceinline__ void red_release_add(unsigned* p, unsigned v) {
    asm volatile("red.release.gpu.global.add.u32 [%0], %1;" :: "l"(p), "r"(v) : "memory");
}
__device__ __forceinline__ unsigned atom_acqrel_add(unsigned* p, unsigned v) {
    unsigned old;
    asm volatile("atom.acq_rel.gpu.global.add.u32 %0, [%1], %2;"
                 : "=r"(old) : "l"(p), "r"(v) : "memory");
    return old;
}

// full grid barrier (NBLK blocks co-resident)
__device__ __forceinline__ void gbar() {
    __syncthreads();
    if (threadIdx.x == 0) {
        unsigned gen = ld_acquire(&g_gen);
        unsigned old = atom_acqrel_add(&g_cnt, 1u);
        if (old == NBLK - 1u) {
            asm volatile("st.relaxed.gpu.global.u32 [%0], %1;" :: "l"(&g_cnt), "r"(0u) : "memory");
            st_release(&g_gen, gen + 1u);
        } else {
            while (ld_acquire(&g_gen) == gen) __nanosleep(32);
        }
    }
    __syncthreads();
}

// up-dot: child rows cb0 (already + g*8), as row from smem (thread's own)
__device__ __forceinline__ float dot_up(const float* __restrict__ cb0,
                                        const float* __restrict__ asr) {
    float sb = 0.f;
    #pragma unroll
    for (int l = 0; l < 4; l++) {
        const float4* ap = (const float4*)(asr + l*8);
        const float4* bp = (const float4*)(cb0 + l*128);
        float4 a0 = ap[0], a1 = ap[1];
        float4 x  = bp[0], y  = bp[1];
        sb += a0.x*x.x + a0.y*x.y + a0.z*x.z + a0.w*x.w
            + a1.x*y.x + a1.y*y.y + a1.z*y.z + a1.w*y.w;
    }
    return sb;
}

// down-dot for one child row (row already + g*8)
__device__ __forceinline__ void dot_dn(const float* __restrict__ row,
                                       const float* __restrict__ asr,
                                       const float* __restrict__ lar,
                                       int l, float& ce, float& ca) {
    const float4* ap = (const float4*)(asr + l*8);
    const float4* lp = (const float4*)(lar + l*8);
    const float4* bp = (const float4*)row;
    float4 a0 = ap[0], a1 = ap[1];
    float4 c0 = lp[0], c1 = lp[1];
    float4 x  = bp[0], y  = bp[1];
    ce = a0.x*x.x + a0.y*x.y + a0.z*x.z + a0.w*x.w
       + a1.x*y.x + a1.y*y.y + a1.z*y.z + a1.w*y.w;
    ca = c0.x*x.x + c0.y*x.y + c0.z*x.z + c0.w*x.w
       + c1.x*y.x + c1.y*y.y + c1.z*y.z + c1.w*y.w;
}

__global__ void __launch_bounds__(1024, 1)
main_kernel(const int* __restrict__ tn,
            const float* __restrict__ a,
            const float* __restrict__ b,
            const float* __restrict__ pi,
            const float* __restrict__ sp,
            float* __restrict__ out)
{
    extern __shared__ float sm[];
    const int tid = threadIdx.x, s = blockIdx.x;
    const int q = tid >> 7, wt = tid & 127, g = wt >> 3, i = wt & 7;
    int* slab = (int*)(sm + OFF_LAB);
    const float* asr = sm + OFF_ASP + wt*32;
    const float* lar = sm + OFF_ALA + wt*32;

    // ---- stage labels ----
    if (tid < 193) {
        int idx = tid, node;
        if      (idx < 128) node = 5461 + 128*s + idx;
        else if (idx < 160) node = 1365 + 32*s + (idx - 128);
        else if (idx < 168) node = 341 + 8*s + (idx - 160);
        else if (idx < 170) node = 85 + 2*s + (idx - 168);
        else if (idx == 170) node = (s < 64) ? (21 + s) : 21;
        else if (idx < 192) node = idx - 171;          // top nodes 0..20
        else                node = 21 + (s >> 1);      // own lvl3 ancestor
        slab[idx] = tn[node * 7];
    }
    // ---- reset flags ----
    if (tid == 0) {
        g_f1[s] = 0u;
        if (s == 0) g_c2 = 0u;
        if (s == 1) g_cfin = 0u;
        if (s == 2) g_cdn = 0u;
    }

    // ================= phase 0a: softmax prep =================
    if (s < 16) {
        if (tid < 256) {
            int w = tid >> 5, ln = tid & 31;
            const float* bp = b + (s*8 + w) * 256;
            float mx = -1e30f;
            for (int m = ln; m < 256; m += 32) mx = fmaxf(mx, bp[m]);
            #pragma unroll
            for (int o = 16; o; o >>= 1) mx = fmaxf(mx, __shfl_xor_sync(0xffffffffu, mx, o));
            float ssum = 0.f;
            for (int m = ln; m < 256; m += 32) ssum += expf(bp[m] - mx);
            #pragma unroll
            for (int o = 16; o; o >>= 1) ssum += __shfl_xor_sync(0xffffffffu, ssum, o);
            float inv = 1.f / ssum, ls = logf(ssum);
            for (int m = ln; m < 256; m += 32) {
                float e = bp[m] - mx;
                g_bt [s*2048 + m*8 + w] = expf(e) * inv;
                g_lbt[s*2048 + m*8 + w] = e - ls;
            }
        }
    } else if (s == 16) {
        float* s_sp = sm + OFF_RED;   // 64 floats scratch
        if (tid < 16) {
            float v[4]; float mx = -1e30f;
            #pragma unroll
            for (int l = 0; l < 4; l++) { v[l] = sp[tid*4 + l]; mx = fmaxf(mx, v[l]); }
            float su = 0.f;
            #pragma unroll
            for (int l = 0; l < 4; l++) { v[l] = expf(v[l] - mx); su += v[l]; }
            float inv = 1.f / su;
            #pragma unroll
            for (int l = 0; l < 4; l++) {
                float smv = v[l] * inv;
                s_sp[tid*4 + l]  = smv;
                g_lsp[tid*4 + l] = logf(smv);
            }
        }
        if (tid < 64) {
            int gg = tid >> 2, l = tid & 3;
            float v[8]; float mx = -1e30f;
            #pragma unroll
            for (int c = 0; c < 8; c++) { v[c] = pi[gg*32 + c*4 + l]; mx = fmaxf(mx, v[c]); }
            float su = 0.f;
            #pragma unroll
            for (int c = 0; c < 8; c++) { v[c] = expf(v[c] - mx); su += v[c]; }
            float inv = 1.f / su, ls = logf(su);
            #pragma unroll
            for (int c = 0; c < 8; c++) {
                g_pit [gg*32 + l*8 + c] = v[c] * inv;
                g_lpit[gg*32 + l*8 + c] = logf(v[c]) - ls;
            }
        }
        __syncthreads();
        if (tid < 512) {   // sm_a: 512 (g,j,l) groups
            int gg = tid >> 5, j = (tid >> 2) & 7, l = tid & 3;
            float v[8]; float mx = -1e30f;
            #pragma unroll
            for (int ii = 0; ii < 8; ii++) {
                v[ii] = a[gg*256 + ii*32 + j*4 + l];
                mx = fmaxf(mx, v[ii]);
            }
            float su = 0.f;
            #pragma unroll
            for (int ii = 0; ii < 8; ii++) { v[ii] = expf(v[ii] - mx); su += v[ii]; }
            float inv = 1.f / su, ls = logf(su);
            float spv = s_sp[gg*4 + l];
            #pragma unroll
            for (int ii = 0; ii < 8; ii++) {
                int idx = ((gg*8 + ii)*4 + l)*8 + j;
                g_asp [idx] = v[ii] * inv * spv;
                g_loga[idx] = logf(v[ii]) - ls;
            }
        }
    } else if (s == 17) {
        if (tid < 16) g_accum[tid] = 0.f;
    }
    gbar();

    // ---- copy asp / build asla into smem (one float4 per thread each) ----
    {
        float4 av = ((const float4*)g_asp)[tid];
        float4 lv = ((const float4*)g_loga)[tid];
        lv.x *= av.x; lv.y *= av.y; lv.z *= av.z; lv.w *= av.w;
        ((float4*)(sm + OFF_ASP))[tid] = av;
        ((float4*)(sm + OFF_ALA))[tid] = lv;
    }
    float lsp[4];
    #pragma unroll
    for (int l = 0; l < 4; l++) lsp[l] = g_lsp[g*4 + l];
    __syncthreads();

    // ================= phase 0b: uptab (1 row per group) =================
    {
        int t = s*8 + q;
        int l = t >> 8, lab = t & 255;
        float lb = g_pit[g*32 + l*8 + i] * g_bt[g*2048 + lab*8 + i];
        lb = __fdividef(lb, sum8(lb));
        float ce = 0.f;
        #pragma unroll
        for (int j = 0; j < 8; j++)
            ce += asr[l*8 + j] * __shfl_sync(0xffffffffu, lb, j, 8);
        g_uptab[t*128 + wt] = ce;
    }
    gbar();

    // ================= phase 1: pair-of-subtrees up =================
    float emis6[4];
    #pragma unroll
    for (int rr = 0; rr < 4; rr++)
        emis6[rr] = g_bt[g*2048 + slab[128 + rr*8 + q]*8 + i];
    #pragma unroll
    for (int rr = 0; rr < 4; rr++) {
        int k = rr*8 + q;
        int lab0 = slab[4*k], lab1 = slab[4*k+1], lab2 = slab[4*k+2], lab3 = slab[4*k+3];
        float sb = g_uptab[(0*256 + lab0)*128 + wt]
                 + g_uptab[(1*256 + lab1)*128 + wt]
                 + g_uptab[(2*256 + lab2)*128 + wt]
                 + g_uptab[(3*256 + lab3)*128 + wt];
        float tmp = emis6[rr] * sb;
        float ts = sum8(tmp);
        sm[OFF_B6 + k*128 + wt] = __fdividef(tmp, ts);
        sm[OFF_S6 + k*128 + wt] = sb;
    }
    __syncthreads();
    // lvl5 (8 nodes, 1 iter: node q)
    {
        float sb = dot_up(sm + OFF_B6 + 4*q*128 + g*8, asr);
        float tmp = g_bt[g*2048 + slab[160 + q]*8 + i] * sb;
        float ts = sum8(tmp);
        sm[OFF_B5 + q*128 + wt] = __fdividef(tmp, ts);
        sm[OFF_S5 + q*128 + wt] = sb;
    }
    __syncthreads();
    // lvl4 (2 nodes, q<2)
    if (q < 2) {
        int t4 = 2*s + q;
        float sb = dot_up(sm + OFF_B5 + 4*q*128 + g*8, asr);
        float tmp = g_bt[g*2048 + slab[168 + q]*8 + i] * sb;
        float ts = sum8(tmp);
        g_beta4[t4*128 + wt] = __fdividef(tmp, ts);
        sm[OFF_S4 + q*128 + wt] = sb;
    }
    __syncthreads();
    if (tid == 0) st_release(&g_f1[s], 1u);

    // ================= lvl3 up (blocks 0..63) =================
    if (s < 64) {
        if (tid == 0) {
            while (ld_acquire(&g_f1[2*s])     == 0u) {}
            while (ld_acquire(&g_f1[2*s + 1]) == 0u) {}
        }
        __syncthreads();
        if (q == 0) {
            float sb = dot_up(&g_beta4[4*s*128 + g*8], asr);
            float tmp = g_bt[g*2048 + slab[170]*8 + i] * sb;
            float ts = sum8(tmp);
            g_beta3 [s*128 + wt] = __fdividef(tmp, ts);
            g_sbeta3[s*128 + wt] = sb;
        }
        __syncthreads();
        if (tid == 0) red_release_add(&g_c2, 1u);
    }

    // ================= dntab build (c2-wait shadow; 1 row per group) =======
    {
        int t = s*8 + q;
        int l = t >> 8, lab = t & 255;
        float lb = g_pit[g*32 + l*8 + i] * g_bt[g*2048 + lab*8 + i];
        lb = __fdividef(lb, sum8(lb));
        float ce = 0.f, ca = 0.f;
        #pragma unroll
        for (int j = 0; j < 8; j++) {
            float v = __shfl_sync(0xffffffffu, lb, j, 8);
            ce += asr[l*8 + j] * v;
            ca += lar[l*8 + j] * v;
        }
        float w = lsp[l] + g_lpit[g*32 + l*8 + i] + g_lbt[g*2048 + lab*8 + i];
        g_dntab[t*128 + wt] = ca + w*ce;
    }
    __syncthreads();
    if (tid == 0) red_release_add(&g_cdn, 1u);

    // ================= wait all lvl3 ready =================
    if (tid == 0) {
        while (ld_acquire(&g_c2) != 64u) __nanosleep(64);
    }
    __syncthreads();

    // copy all 64 beta3 rows to smem (2 float4 per thread)
    {
        float4* dst = (float4*)(sm + OFF_TOP);
        const float4* src = (const float4*)g_beta3;
        dst[tid]        = src[tid];
        dst[tid + 1024] = src[tid + 1024];
    }
    __syncthreads();

    // ================= redundant top: up lvl2/lvl1/root =================
    float acc = 0.f;
    #pragma unroll
    for (int rr = 0; rr < 2; rr++) {
        int k = rr*8 + q;
        float sb = dot_up(sm + OFF_TOP + 4*k*128 + g*8, asr);
        float tmp = g_bt[g*2048 + slab[176 + k]*8 + i] * sb;
        float ts = sum8(tmp);
        sm[OFF_B2 + k*128 + wt] = __fdividef(tmp, ts);
        sm[OFF_S2 + k*128 + wt] = sb;
    }
    __syncthreads();
    if (q < 4) {
        float sb = dot_up(sm + OFF_B2 + 4*q*128 + g*8, asr);
        float tmp = g_bt[g*2048 + slab[172 + q]*8 + i] * sb;
        float ts = sum8(tmp);
        sm[OFF_B1 + q*128 + wt] = __fdividef(tmp, ts);
        sm[OFF_S1 + q*128 + wt] = sb;
    }
    __syncthreads();
    // root up+down (group 0)
    if (q == 0) {
        float sb = dot_up(sm + OFF_B1 + g*8, asr);
        int lab0 = slab[171];
        float tmp = g_bt[g*2048 + lab0*8 + i] * sb;
        float ts = sum8(tmp);
        float betar = __fdividef(tmp, ts);
        float pe = __fdividef(betar, sb);
        if (s == 0) acc += betar * g_lbt[g*2048 + lab0*8 + i];
        #pragma unroll
        for (int l = 0; l < 4; l++) {
            float ce, ca;
            dot_dn(sm + OFF_B1 + l*128 + g*8, asr, lar, l, ce, ca);
            ce *= pe;
            sm[OFF_E1 + l*128 + wt] = ce;
            if (s == 0) acc += pe*ca + lsp[l]*ce;
        }
    }
    __syncthreads();
    // down lvl1 (groups 0..3 = nodes 0..3)
    if (q < 4) {
        float epsv = sm[OFF_E1 + q*128 + wt];
        float pe = __fdividef(epsv, sm[OFF_S1 + q*128 + wt]);
        if (s == 0) acc += epsv * g_lbt[g*2048 + slab[172 + q]*8 + i];
        #pragma unroll
        for (int l = 0; l < 4; l++) {
            float ce, ca;
            dot_dn(sm + OFF_B2 + (4*q + l)*128 + g*8, asr, lar, l, ce, ca);
            ce *= pe;
            sm[OFF_E2 + (4*q + l)*128 + wt] = ce;
            if (s == 0) acc += pe*ca + lsp[l]*ce;
        }
    }
    __syncthreads();
    // down lvl2: block0 full (acc); others own node only
    if (s == 0) {
        #pragma unroll
        for (int rr = 0; rr < 2; rr++) {
            int k = rr*8 + q;
            float epsv = sm[OFF_E2 + k*128 + wt];
            float pe = __fdividef(epsv, sm[OFF_S2 + k*128 + wt]);
            acc += epsv * g_lbt[g*2048 + slab[176 + k]*8 + i];
            #pragma unroll
            for (int l = 0; l < 4; l++) {
                float ce, ca;
                dot_dn(sm + OFF_TOP + (4*k + l)*128 + g*8, asr, lar, l, ce, ca);
                ce *= pe;
                acc += pe*ca + lsp[l]*ce;
                if (4*k + l == 0) sm[OFF_E3 + wt] = ce;
            }
        }
    } else if (q == 0) {
        int t = s >> 1, p2 = t >> 2, lc = t & 3;
        float epsv = sm[OFF_E2 + p2*128 + wt];
        float pe = __fdividef(epsv, sm[OFF_S2 + p2*128 + wt]);
        const float4* ap = (const float4*)(asr + lc*8);
        const float4* bp = (const float4*)(sm + OFF_TOP + (4*p2 + lc)*128 + g*8);
        float4 a0 = ap[0], a1 = ap[1];
        float4 x = bp[0], y = bp[1];
        float ce = a0.x*x.x + a0.y*x.y + a0.z*x.z + a0.w*x.w
                 + a1.x*y.x + a1.y*y.y + a1.z*y.z + a1.w*y.w;
        sm[OFF_E3 + wt] = ce * pe;
    }
    // lvl3 down (group 0)
    if (q == 0) {
        int t = s >> 1;
        int half = s & 1;
        float eps3 = sm[OFF_E3 + wt];
        float pe3 = __fdividef(eps3, g_sbeta3[t*128 + wt]);
        if (half == 0) acc += eps3 * g_lbt[g*2048 + slab[192]*8 + i];
        #pragma unroll
        for (int l = 0; l < 4; l++) {
            float ce, ca;
            dot_dn(&g_beta4[(4*t + l)*128 + g*8], asr, lar, l, ce, ca);
            ce *= pe3;
            int lown = l - 2*half;
            if (lown == 0 || lown == 1) {
                acc += pe3*ca + lsp[l]*ce;
                sm[OFF_E4 + lown*128 + wt] = ce;
            }
        }
    }
    __syncthreads();

    // ================= phase 3: pair-of-subtrees down =================
    if (q < 2) {
        float epsv = sm[OFF_E4 + q*128 + wt];
        float pe = __fdividef(epsv, sm[OFF_S4 + q*128 + wt]);
        acc += epsv * g_lbt[g*2048 + slab[168 + q]*8 + i];
        #pragma unroll
        for (int l = 0; l < 4; l++) {
            float ce, ca;
            dot_dn(sm + OFF_B5 + (4*q + l)*128 + g*8, asr, lar, l, ce, ca);
            ce *= pe;
            sm[OFF_E5 + (4*q + l)*128 + wt] = ce;
            acc += pe*ca + lsp[l]*ce;
        }
    }
    __syncthreads();
    // lvl5 down (node q)
    {
        float epsv = sm[OFF_E5 + q*128 + wt];
        float pe = __fdividef(epsv, sm[OFF_S5 + q*128 + wt]);
        acc += epsv * g_lbt[g*2048 + slab[160 + q]*8 + i];
        #pragma unroll
        for (int l = 0; l < 4; l++) {
            float ce, ca;
            dot_dn(sm + OFF_B6 + (4*q + l)*128 + g*8, asr, lar, l, ce, ca);
            ce *= pe;
            sm[OFF_E6 + (4*q + l)*128 + wt] = ce;
            acc += pe*ca + lsp[l]*ce;
        }
    }
    __syncthreads();
    // wait dntab complete (normally already satisfied)
    if (tid == 0) {
        while (ld_acquire(&g_cdn) != (unsigned)NBLK) {}
    }
    __syncthreads();
    // lvl6 down (4 iters): leaf children via dn_tab
    float lemis6[4];
    #pragma unroll
    for (int rr = 0; rr < 4; rr++)
        lemis6[rr] = g_lbt[g*2048 + slab[128 + rr*8 + q]*8 + i];
    #pragma unroll
    for (int rr = 0; rr < 4; rr++) {
        int k = rr*8 + q;
        int lab0 = slab[4*k], lab1 = slab[4*k+1], lab2 = slab[4*k+2], lab3 = slab[4*k+3];
        float epsv = sm[OFF_E6 + k*128 + wt];
        float pe = __fdividef(epsv, sm[OFF_S6 + k*128 + wt]);
        acc += epsv * lemis6[rr];
        float d = g_dntab[(0*256 + lab0)*128 + wt]
                + g_dntab[(1*256 + lab1)*128 + wt]
                + g_dntab[(2*256 + lab2)*128 + wt]
                + g_dntab[(3*256 + lab3)*128 + wt];
        acc += pe * d;
    }

    // ================= reduce + finish ticket =================
    acc = sum8(acc);
    if (i == 0) sm[OFF_RED + q*16 + g] = acc;
    __syncthreads();
    if (tid < 16) {
        float p = 0.f;
        #pragma unroll
        for (int k = 0; k < 8; k++) p += sm[OFF_RED + k*16 + tid];
        atomicAdd(&g_accum[tid], p);
    }
    __syncthreads();
    unsigned* plast = (unsigned*)(sm + OFF_LAST);
    if (tid == 0) {
        unsigned old = atom_acqrel_add(&g_cfin, 1u);
        *plast = (old == NBLK - 1u) ? 1u : 0u;
    }
    __syncthreads();
    if (*plast && tid < 16)
        out[tid] = *(volatile float*)&g_accum[tid];
}

// ---------------------------------------------------------------------------
extern "C" void kernel_launch(void* const* d_in, const int* in_sizes, int n_in,
                              void* d_out, int out_size)
{
    const int*   tn = (const int*)  d_in[0];
    const float* a  = (const float*)d_in[2];
    const float* b  = (const float*)d_in[3];
    const float* pi = (const float*)d_in[4];
    const float* sp = (const float*)d_in[5];
    float* out = (float*)d_out;

    cudaFuncSetAttribute(main_kernel,
                         cudaFuncAttributeMaxDynamicSharedMemorySize,
                         SMEM_FLOATS * 4);
    main_kernel<<<NBLK, 1024, SMEM_FLOATS * 4>>>(tn, a, b, pi, sp, out);
}

// round 11
// speedup vs baseline: 1.7677x; 1.7677x over previous
#include <cuda_runtime.h>

// ---------------------------------------------------------------------------
// BottomUpHTMM — complete 4-ary tree depth 7, single persistent kernel.
// 128 blocks x 512 threads (4 groups of 128 = (g,c)); each block owns two
// level-4 subtrees. as/la tables in REGISTERS (R10 showed smem tables = bank
// conflicts). Blocked node->group assignment + named barriers at lvl6<->lvl5.
// Redundant top per block; flag-based sync, pure spins.
// ---------------------------------------------------------------------------

#define GC    128
#define NBLK  128

// tables
__device__ float g_asp [4096];      // a_sp[g][i][l][j]   (wt=g*8+i -> wt*32+l*8+j)
__device__ float g_loga[4096];      // log sm_a
__device__ float g_bt  [16*256*8];  // sm_b[g][m][c]
__device__ float g_lbt [16*256*8];
__device__ float g_pit [512];       // sm_pi[g][pos][c]
__device__ float g_lpit[512];
__device__ float g_lsp [64];        // log sm_sp[g][l]

// leaf contribution tables: index (l*256+lab)*128 + wt
__device__ float g_uptab[1024 * GC];
__device__ float g_dntab[1024 * GC];

// cross-block state
__device__ float g_beta4 [256 * GC];
__device__ float g_beta3 [64 * GC];
__device__ float g_sbeta3[64 * GC];
__device__ float g_accum [16];

// sync state
__device__ unsigned g_cnt = 0;
__device__ unsigned g_gen = 0;
__device__ unsigned g_f1[NBLK];     // beta4 pair of block s ready
__device__ unsigned g_c2;           // # lvl3 nodes done
__device__ unsigned g_cfin;         // finish ticket

// shared-memory layout (floats; rows of 128)
#define OFF_B6    0        // 32 rows lvl6 beta
#define OFF_S6    4096     // 32 rows lvl6 sbeta
#define OFF_B5    8192     // 8 rows lvl5 beta
#define OFF_S5    9216     // 8 rows lvl5 sbeta
#define OFF_S4    10240    // 2 rows lvl4 sbeta
#define OFF_E5    10496    // 8 rows lvl5 eps
#define OFF_E6    11520    // 32 rows lvl6 eps
#define OFF_TOP   15616    // 64 rows beta3 copy
#define OFF_B2    23808    // 16 rows lvl2 beta
#define OFF_S2    25856    // 16 rows lvl2 sbeta
#define OFF_B1    27904    // 4 rows lvl1 beta
#define OFF_S1    28416    // 4 rows lvl1 sbeta
#define OFF_E1    28928    // 4 rows lvl1 eps
#define OFF_E2    29440    // 16 rows lvl2 eps
#define OFF_E3    31488    // 1 row  own lvl3 eps
#define OFF_E4    31616    // 2 rows own lvl4 eps
#define OFF_RED   31872    // 64
#define OFF_LAB   31936    // 208 ints
#define OFF_LAST  32144    // 1
#define SMEM_FLOATS 32148  // ~125.6 KB

__device__ __forceinline__ float sum8(float v) {
    v += __shfl_xor_sync(0xffffffffu, v, 4);
    v += __shfl_xor_sync(0xffffffffu, v, 2);
    v += __shfl_xor_sync(0xffffffffu, v, 1);
    return v;
}

__device__ __forceinline__ void load_tab(const float* __restrict__ base, int wt,
                                         float (&r)[4][8]) {
    const float4* p = (const float4*)(base + wt * 32);
    #pragma unroll
    for (int l = 0; l < 4; l++) {
        float4 a = p[2*l], b = p[2*l + 1];
        r[l][0]=a.x; r[l][1]=a.y; r[l][2]=a.z; r[l][3]=a.w;
        r[l][4]=b.x; r[l][5]=b.y; r[l][6]=b.z; r[l][7]=b.w;
    }
}

// group-local barrier (4 warps, named barrier 1+q)
__device__ __forceinline__ void gsync(int q) {
    asm volatile("bar.sync %0, 128;" :: "r"(1 + q) : "memory");
}

// ---- acquire/release helpers ----
__device__ __forceinline__ void st_release(unsigned* p, unsigned v) {
    asm volatile("st.release.gpu.global.u32 [%0], %1;" :: "l"(p), "r"(v) : "memory");
}
__device__ __forceinline__ unsigned ld_acquire(unsigned* p) {
    unsigned v;
    asm volatile("ld.acquire.gpu.global.u32 %0, [%1];" : "=r"(v) : "l"(p) : "memory");
    return v;
}
__device__ __forceinline__ void red_release_add(unsigned* p, unsigned v) {
    asm volatile("red.release.gpu.global.add.u32 [%0], %1;" :: "l"(p), "r"(v) : "memory");
}
__device__ __forceinline__ unsigned atom_acqrel_add(unsigned* p, unsigned v) {
    unsigned old;
    asm volatile("atom.acq_rel.gpu.global.add.u32 %0, [%1], %2;"
                 : "=r"(old) : "l"(p), "r"(v) : "memory");
    return old;
}

// full grid barrier (NBLK blocks co-resident)
__device__ __forceinline__ void gbar() {
    __syncthreads();
    if (threadIdx.x == 0) {
        unsigned gen = ld_acquire(&g_gen);
        unsigned old = atom_acqrel_add(&g_cnt, 1u);
        if (old == NBLK - 1u) {
            asm volatile("st.relaxed.gpu.global.u32 [%0], %1;" :: "l"(&g_cnt), "r"(0u) : "memory");
            st_release(&g_gen, gen + 1u);
        } else {
            while (ld_acquire(&g_gen) == gen) {}
        }
    }
    __syncthreads();
}

__device__ __forceinline__ float dot_up(const float* __restrict__ cb0,
                                        const float (&as)[4][8], int g) {
    float sb = 0.f;
    #pragma unroll
    for (int l = 0; l < 4; l++) {
        const float* bv = cb0 + l*128 + g*8;
        #pragma unroll
        for (int j = 0; j < 8; j++) sb += as[l][j] * bv[j];
    }
    return sb;
}

__global__ void __launch_bounds__(512, 1)
main_kernel(const int* __restrict__ tn,
            const float* __restrict__ a,
            const float* __restrict__ b,
            const float* __restrict__ pi,
            const float* __restrict__ sp,
            float* __restrict__ out)
{
    extern __shared__ float sm[];
    const int tid = threadIdx.x, s = blockIdx.x;
    const int q = tid >> 7, wt = tid & 127, g = wt >> 3, i = wt & 7;
    int* slab = (int*)(sm + OFF_LAB);

    // ---- stage labels ----
    if (tid < 193) {
        int idx = tid, node;
        if      (idx < 128) node = 5461 + 128*s + idx;
        else if (idx < 160) node = 1365 + 32*s + (idx - 128);
        else if (idx < 168) node = 341 + 8*s + (idx - 160);
        else if (idx < 170) node = 85 + 2*s + (idx - 168);
        else if (idx == 170) node = (s < 64) ? (21 + s) : 21;
        else if (idx < 192) node = idx - 171;          // top nodes 0..20
        else                node = 21 + (s >> 1);      // own lvl3 ancestor
        slab[idx] = tn[node * 7];
    }
    // ---- reset flags ----
    if (tid == 0) {
        g_f1[s] = 0u;
        if (s == 0) g_c2 = 0u;
        if (s == 1) g_cfin = 0u;
    }

    // ================= phase 0a: softmax prep =================
    if (s < 16) {
        if (tid < 256) {
            int w = tid >> 5, ln = tid & 31;
            const float* bp = b + (s*8 + w) * 256;
            float mx = -1e30f;
            for (int m = ln; m < 256; m += 32) mx = fmaxf(mx, bp[m]);
            #pragma unroll
            for (int o = 16; o; o >>= 1) mx = fmaxf(mx, __shfl_xor_sync(0xffffffffu, mx, o));
            float ssum = 0.f;
            for (int m = ln; m < 256; m += 32) ssum += expf(bp[m] - mx);
            #pragma unroll
            for (int o = 16; o; o >>= 1) ssum += __shfl_xor_sync(0xffffffffu, ssum, o);
            float inv = 1.f / ssum, ls = logf(ssum);
            for (int m = ln; m < 256; m += 32) {
                float e = bp[m] - mx;
                g_bt [s*2048 + m*8 + w] = expf(e) * inv;
                g_lbt[s*2048 + m*8 + w] = e - ls;
            }
        }
    } else if (s == 16) {
        float* s_sp = sm + OFF_RED;
        if (tid < 16) {
            float v[4]; float mx = -1e30f;
            #pragma unroll
            for (int l = 0; l < 4; l++) { v[l] = sp[tid*4 + l]; mx = fmaxf(mx, v[l]); }
            float su = 0.f;
            #pragma unroll
            for (int l = 0; l < 4; l++) { v[l] = expf(v[l] - mx); su += v[l]; }
            float inv = 1.f / su;
            #pragma unroll
            for (int l = 0; l < 4; l++) {
                float smv = v[l] * inv;
                s_sp[tid*4 + l]  = smv;
                g_lsp[tid*4 + l] = logf(smv);
            }
        }
        if (tid < 64) {
            int gg = tid >> 2, l = tid & 3;
            float v[8]; float mx = -1e30f;
            #pragma unroll
            for (int c = 0; c < 8; c++) { v[c] = pi[gg*32 + c*4 + l]; mx = fmaxf(mx, v[c]); }
            float su = 0.f;
            #pragma unroll
            for (int c = 0; c < 8; c++) { v[c] = expf(v[c] - mx); su += v[c]; }
            float inv = 1.f / su, ls = logf(su);
            #pragma unroll
            for (int c = 0; c < 8; c++) {
                g_pit [gg*32 + l*8 + c] = v[c] * inv;
                g_lpit[gg*32 + l*8 + c] = logf(v[c]) - ls;
            }
        }
        __syncthreads();
        {   // sm_a: 512 (g,j,l) groups, one per thread
            int gg = tid >> 5, j = (tid >> 2) & 7, l = tid & 3;
            float v[8]; float mx = -1e30f;
            #pragma unroll
            for (int ii = 0; ii < 8; ii++) {
                v[ii] = a[gg*256 + ii*32 + j*4 + l];
                mx = fmaxf(mx, v[ii]);
            }
            float su = 0.f;
            #pragma unroll
            for (int ii = 0; ii < 8; ii++) { v[ii] = expf(v[ii] - mx); su += v[ii]; }
            float inv = 1.f / su, ls = logf(su);
            float spv = s_sp[gg*4 + l];
            #pragma unroll
            for (int ii = 0; ii < 8; ii++) {
                int idx = ((gg*8 + ii)*4 + l)*8 + j;
                g_asp [idx] = v[ii] * inv * spv;
                g_loga[idx] = logf(v[ii]) - ls;
            }
        }
    } else if (s == 17) {
        if (tid < 16) g_accum[tid] = 0.f;
    }
    gbar();

    // tables in registers
    float as[4][8], la[4][8];
    load_tab(g_asp, wt, as);
    load_tab(g_loga, wt, la);
    #pragma unroll
    for (int l = 0; l < 4; l++)
        #pragma unroll
        for (int j = 0; j < 8; j++) la[l][j] *= as[l][j];
    float lsp[4];
    #pragma unroll
    for (int l = 0; l < 4; l++) lsp[l] = g_lsp[g*4 + l];

    // ================= phase 0b: leaf tables (up + dn) =================
    #pragma unroll
    for (int r = 0; r < 2; r++) {
        int t = (s*4 + q) + 512*r;
        int l = t >> 8, lab = t & 255;
        float lb = g_pit[g*32 + l*8 + i] * g_bt[g*2048 + lab*8 + i];
        lb = __fdividef(lb, sum8(lb));
        float ce = 0.f, ca = 0.f;
        #pragma unroll
        for (int j = 0; j < 8; j++) {
            float v = __shfl_sync(0xffffffffu, lb, j, 8);
            ce += as[l][j]*v; ca += la[l][j]*v;
        }
        float w = lsp[l] + g_lpit[g*32 + l*8 + i] + g_lbt[g*2048 + lab*8 + i];
        g_uptab[t*128 + wt] = ce;
        g_dntab[t*128 + wt] = ca + w*ce;
    }
    gbar();

    // ================= phase 1: pair-of-subtrees up =================
    // lvl6 (32 nodes/block), BLOCKED: group q owns k = q*8 .. q*8+7
    float emis6[8];
    #pragma unroll
    for (int rr = 0; rr < 8; rr++)
        emis6[rr] = g_bt[g*2048 + slab[128 + q*8 + rr]*8 + i];
    #pragma unroll 4
    for (int rr = 0; rr < 8; rr++) {
        int k = q*8 + rr;
        int lab0 = slab[4*k], lab1 = slab[4*k+1], lab2 = slab[4*k+2], lab3 = slab[4*k+3];
        float sb = g_uptab[(0*256 + lab0)*128 + wt]
                 + g_uptab[(1*256 + lab1)*128 + wt]
                 + g_uptab[(2*256 + lab2)*128 + wt]
                 + g_uptab[(3*256 + lab3)*128 + wt];
        float tmp = emis6[rr] * sb;
        float ts = sum8(tmp);
        sm[OFF_B6 + k*128 + wt] = __fdividef(tmp, ts);
        sm[OFF_S6 + k*128 + wt] = sb;
    }
    gsync(q);   // group-local: lvl5 nodes 2q,2q+1 consume only this group's rows
    // lvl5 (8 nodes), BLOCKED: group q owns nodes 2q, 2q+1
    #pragma unroll
    for (int rr = 0; rr < 2; rr++) {
        int k = 2*q + rr;
        float sb = dot_up(sm + OFF_B6 + 4*k*128, as, g);
        float tmp = g_bt[g*2048 + slab[160 + k]*8 + i] * sb;
        float ts = sum8(tmp);
        sm[OFF_B5 + k*128 + wt] = __fdividef(tmp, ts);
        sm[OFF_S5 + k*128 + wt] = sb;
    }
    __syncthreads();   // lvl4 crosses groups
    // lvl4 (2, q<2) -> global beta4
    if (q < 2) {
        int t4 = 2*s + q;
        float sb = dot_up(sm + OFF_B5 + 4*q*128, as, g);
        float tmp = g_bt[g*2048 + slab[168 + q]*8 + i] * sb;
        float ts = sum8(tmp);
        g_beta4[t4*128 + wt] = __fdividef(tmp, ts);
        sm[OFF_S4 + q*128 + wt] = sb;
    }
    __syncthreads();
    if (tid == 0) st_release(&g_f1[s], 1u);

    // ================= lvl3 up (blocks 0..63) =================
    if (s < 64) {
        if (tid == 0) {
            while (ld_acquire(&g_f1[2*s])     == 0u) {}
            while (ld_acquire(&g_f1[2*s + 1]) == 0u) {}
        }
        __syncthreads();
        if (q == 0) {
            float sb = dot_up(&g_beta4[4*s*128], as, g);
            float tmp = g_bt[g*2048 + slab[170]*8 + i] * sb;
            float ts = sum8(tmp);
            g_beta3 [s*128 + wt] = __fdividef(tmp, ts);
            g_sbeta3[s*128 + wt] = sb;
        }
        __syncthreads();
        if (tid == 0) red_release_add(&g_c2, 1u);
    }

    // ================= wait all lvl3 ready =================
    if (tid == 0) {
        while (ld_acquire(&g_c2) != 64u) {}
    }
    __syncthreads();

    // copy all 64 beta3 rows to smem
    {
        float4* dst = (float4*)(sm + OFF_TOP);
        const float4* src = (const float4*)g_beta3;
        #pragma unroll
        for (int r = 0; r < 4; r++) dst[tid + r*512] = src[tid + r*512];
    }
    __syncthreads();

    // ================= redundant top: up lvl2/lvl1/root =================
    float acc = 0.f;
    #pragma unroll 2
    for (int rr = 0; rr < 4; rr++) {
        int k = rr*4 + q;
        float sb = dot_up(sm + OFF_TOP + 4*k*128, as, g);
        float tmp = g_bt[g*2048 + slab[176 + k]*8 + i] * sb;
        float ts = sum8(tmp);
        sm[OFF_B2 + k*128 + wt] = __fdividef(tmp, ts);
        sm[OFF_S2 + k*128 + wt] = sb;
    }
    __syncthreads();
    {
        float sb = dot_up(sm + OFF_B2 + 4*q*128, as, g);
        float tmp = g_bt[g*2048 + slab[172 + q]*8 + i] * sb;
        float ts = sum8(tmp);
        sm[OFF_B1 + q*128 + wt] = __fdividef(tmp, ts);
        sm[OFF_S1 + q*128 + wt] = sb;
    }
    __syncthreads();
    // root up+down (group 0)
    if (q == 0) {
        float sb = dot_up(sm + OFF_B1, as, g);
        int lab0 = slab[171];
        float tmp = g_bt[g*2048 + lab0*8 + i] * sb;
        float ts = sum8(tmp);
        float betar = __fdividef(tmp, ts);
        float pe = __fdividef(betar, sb);
        if (s == 0) acc += betar * g_lbt[g*2048 + lab0*8 + i];
        #pragma unroll
        for (int l = 0; l < 4; l++) {
            const float* bv = sm + OFF_B1 + l*128 + g*8;
            float ce = 0.f, ca = 0.f;
            #pragma unroll
            for (int j = 0; j < 8; j++) { ce += as[l][j]*bv[j]; ca += la[l][j]*bv[j]; }
            ce *= pe;
            sm[OFF_E1 + l*128 + wt] = ce;
            if (s == 0) acc += pe*ca + lsp[l]*ce;
        }
    }
    __syncthreads();
    // down lvl1 (group q = node q)
    {
        float epsv = sm[OFF_E1 + q*128 + wt];
        float pe = __fdividef(epsv, sm[OFF_S1 + q*128 + wt]);
        if (s == 0) acc += epsv * g_lbt[g*2048 + slab[172 + q]*8 + i];
        #pragma unroll
        for (int l = 0; l < 4; l++) {
            const float* bv = sm + OFF_B2 + (4*q + l)*128 + g*8;
            float ce = 0.f, ca = 0.f;
            #pragma unroll
            for (int j = 0; j < 8; j++) { ce += as[l][j]*bv[j]; ca += la[l][j]*bv[j]; }
            ce *= pe;
            sm[OFF_E2 + (4*q + l)*128 + wt] = ce;
            if (s == 0) acc += pe*ca + lsp[l]*ce;
        }
    }
    __syncthreads();
    // down lvl2: block0 full (acc); others own node only
    if (s == 0) {
        #pragma unroll 2
        for (int rr = 0; rr < 4; rr++) {
            int k = rr*4 + q;
            float epsv = sm[OFF_E2 + k*128 + wt];
            float pe = __fdividef(epsv, sm[OFF_S2 + k*128 + wt]);
            acc += epsv * g_lbt[g*2048 + slab[176 + k]*8 + i];
            #pragma unroll
            for (int l = 0; l < 4; l++) {
                const float* bv = sm + OFF_TOP + (4*k + l)*128 + g*8;
                float ce = 0.f, ca = 0.f;
                #pragma unroll
                for (int j = 0; j < 8; j++) { ce += as[l][j]*bv[j]; ca += la[l][j]*bv[j]; }
                ce *= pe;
                acc += pe*ca + lsp[l]*ce;
                if (4*k + l == 0) sm[OFF_E3 + wt] = ce;
            }
        }
    } else if (q == 0) {
        int t = s >> 1, p2 = t >> 2, lc = t & 3;
        float epsv = sm[OFF_E2 + p2*128 + wt];
        float pe = __fdividef(epsv, sm[OFF_S2 + p2*128 + wt]);
        const float* bv = sm + OFF_TOP + (4*p2 + lc)*128 + g*8;
        float ce = 0.f;
        #pragma unroll
        for (int j = 0; j < 8; j++) ce += as[lc][j]*bv[j];
        sm[OFF_E3 + wt] = ce * pe;
    }
    // lvl3 down (group 0; E3 produced/consumed by same threads)
    if (q == 0) {
        int t = s >> 1;
        int half = s & 1;
        float eps3 = sm[OFF_E3 + wt];
        float pe3 = __fdividef(eps3, g_sbeta3[t*128 + wt]);
        if (half == 0) acc += eps3 * g_lbt[g*2048 + slab[192]*8 + i];
        #pragma unroll
        for (int l = 0; l < 4; l++) {
            const float* bv = &g_beta4[(4*t + l)*128 + g*8];
            float ce = 0.f, ca = 0.f;
            #pragma unroll
            for (int j = 0; j < 8; j++) { ce += as[l][j]*bv[j]; ca += la[l][j]*bv[j]; }
            ce *= pe3;
            int lown = l - 2*half;
            if (lown == 0 || lown == 1) {
                acc += pe3*ca + lsp[l]*ce;
                sm[OFF_E4 + lown*128 + wt] = ce;
            }
        }
    }
    __syncthreads();

    // ================= phase 3: pair-of-subtrees down =================
    if (q < 2) {
        float epsv = sm[OFF_E4 + q*128 + wt];
        float pe = __fdividef(epsv, sm[OFF_S4 + q*128 + wt]);
        acc += epsv * g_lbt[g*2048 + slab[168 + q]*8 + i];
        #pragma unroll
        for (int l = 0; l < 4; l++) {
            const float* bv = sm + OFF_B5 + (4*q + l)*128 + g*8;
            float ce = 0.f, ca = 0.f;
            #pragma unroll
            for (int j = 0; j < 8; j++) { ce += as[l][j]*bv[j]; ca += la[l][j]*bv[j]; }
            ce *= pe;
            sm[OFF_E5 + (4*q + l)*128 + wt] = ce;
            acc += pe*ca + lsp[l]*ce;
        }
    }
    __syncthreads();   // E5 crosses groups
    // lvl5 down (8), BLOCKED: group q owns nodes 2q, 2q+1
    #pragma unroll
    for (int rr = 0; rr < 2; rr++) {
        int k = 2*q + rr;
        float epsv = sm[OFF_E5 + k*128 + wt];
        float pe = __fdividef(epsv, sm[OFF_S5 + k*128 + wt]);
        acc += epsv * g_lbt[g*2048 + slab[160 + k]*8 + i];
        #pragma unroll
        for (int l = 0; l < 4; l++) {
            const float* bv = sm + OFF_B6 + (4*k + l)*128 + g*8;
            float ce = 0.f, ca = 0.f;
            #pragma unroll
            for (int j = 0; j < 8; j++) { ce += as[l][j]*bv[j]; ca += la[l][j]*bv[j]; }
            ce *= pe;
            sm[OFF_E6 + (4*k + l)*128 + wt] = ce;
            acc += pe*ca + lsp[l]*ce;
        }
    }
    gsync(q);   // group-local: lvl6 nodes q*8.. consume only this group's rows
    // lvl6 down (32), BLOCKED: leaf children via dn_tab
    float lemis6[8];
    #pragma unroll
    for (int rr = 0; rr < 8; rr++)
        lemis6[rr] = g_lbt[g*2048 + slab[128 + q*8 + rr]*8 + i];
    #pragma unroll 4
    for (int rr = 0; rr < 8; rr++) {
        int k = q*8 + rr;
        int lab0 = slab[4*k], lab1 = slab[4*k+1], lab2 = slab[4*k+2], lab3 = slab[4*k+3];
        float epsv = sm[OFF_E6 + k*128 + wt];
        float pe = __fdividef(epsv, sm[OFF_S6 + k*128 + wt]);
        acc += epsv * lemis6[rr];
        float d = g_dntab[(0*256 + lab0)*128 + wt]
                + g_dntab[(1*256 + lab1)*128 + wt]
                + g_dntab[(2*256 + lab2)*128 + wt]
                + g_dntab[(3*256 + lab3)*128 + wt];
        acc += pe * d;
    }

    // ================= reduce + finish ticket =================
    acc = sum8(acc);
    if (i == 0) sm[OFF_RED + q*16 + g] = acc;
    __syncthreads();
    if (tid < 16) {
        float p = sm[OFF_RED + tid] + sm[OFF_RED + 16 + tid]
                + sm[OFF_RED + 32 + tid] + sm[OFF_RED + 48 + tid];
        atomicAdd(&g_accum[tid], p);
    }
    __syncthreads();
    unsigned* plast = (unsigned*)(sm + OFF_LAST);
    if (tid == 0) {
        unsigned old = atom_acqrel_add(&g_cfin, 1u);
        *plast = (old == NBLK - 1u) ? 1u : 0u;
    }
    __syncthreads();
    if (*plast && tid < 16)
        out[tid] = *(volatile float*)&g_accum[tid];
}

// ---------------------------------------------------------------------------
extern "C" void kernel_launch(void* const* d_in, const int* in_sizes, int n_in,
                              void* d_out, int out_size)
{
    const int*   tn = (const int*)  d_in[0];
    const float* a  = (const float*)d_in[2];
    const float* b  = (const float*)d_in[3];
    const float* pi = (const float*)d_in[4];
    const float* sp = (const float*)d_in[5];
    float* out = (float*)d_out;

    cudaFuncSetAttribute(main_kernel,
                         cudaFuncAttributeMaxDynamicSharedMemorySize,
                         SMEM_FLOATS * 4);
    main_kernel<<<NBLK, 512, SMEM_FLOATS * 4>>>(tn, a, b, pi, sp, out);
}

// round 12
// speedup vs baseline: 1.9712x; 1.1151x over previous
#include <cuda_runtime.h>

// ---------------------------------------------------------------------------
// BottomUpHTMM — complete 4-ary tree depth 7, single persistent kernel.
// 128 blocks x 1024 threads (8 groups of 128 = (g,c)); each block owns two
// level-4 subtrees. a_sp / a_sp*log(a) tables in PADDED shared memory
// (stride 33 floats -> conflict-free scalar LDS) => regs<=64 => 32 warps/SM.
// Blocked node->group mapping + named barriers. Redundant top per block.
// ---------------------------------------------------------------------------

#define GC    128
#define NBLK  128

// tables (global)
__device__ float g_asp [4096];      // a_sp[g][i][l][j]   (wt=g*8+i -> wt*32+l*8+j)
__device__ float g_loga[4096];      // log sm_a
__device__ float g_bt  [16*256*8];  // sm_b[g][m][c]
__device__ float g_lbt [16*256*8];
__device__ float g_pit [512];       // sm_pi[g][pos][c]
__device__ float g_lpit[512];
__device__ float g_lsp [64];        // log sm_sp[g][l]

// leaf contribution tables: index (l*256+lab)*128 + wt
__device__ float g_uptab[1024 * GC];
__device__ float g_dntab[1024 * GC];

// cross-block state
__device__ float g_beta4 [256 * GC];
__device__ float g_beta3 [64 * GC];
__device__ float g_sbeta3[64 * GC];
__device__ float g_accum [16];

// sync state
__device__ unsigned g_cnt = 0;
__device__ unsigned g_gen = 0;
__device__ unsigned g_f1[NBLK];     // beta4 pair of block s ready
__device__ unsigned g_c2;           // # lvl3 nodes done
__device__ unsigned g_cfin;         // finish ticket

// shared-memory layout (floats)
#define OFF_ASP   0        // 128 rows x 33 (padded, conflict-free)
#define OFF_ALA   4224     // 128 rows x 33
#define OFF_B6    8448     // 32 rows x 128
#define OFF_S6    12544    // 32 rows
#define OFF_B5    16640    // 8 rows
#define OFF_S5    17664    // 8 rows
#define OFF_S4    18688    // 2 rows
#define OFF_E5    18944    // 8 rows
#define OFF_E6    19968    // 32 rows
#define OFF_TOP   24064    // 64 rows beta3 copy
#define OFF_B2    32256    // 16 rows
#define OFF_S2    34304    // 16 rows
#define OFF_B1    36352    // 4 rows
#define OFF_S1    36864    // 4 rows
#define OFF_E1    37376    // 4 rows
#define OFF_E2    37888    // 16 rows
#define OFF_E3    39936    // 1 row
#define OFF_E4    40064    // 2 rows
#define OFF_RED   40320    // 128
#define OFF_LAB   40448    // 208 ints
#define OFF_LAST  40656    // 1
#define SMEM_FLOATS 40660  // ~158.8 KB

__device__ __forceinline__ float sum8(float v) {
    v += __shfl_xor_sync(0xffffffffu, v, 4);
    v += __shfl_xor_sync(0xffffffffu, v, 2);
    v += __shfl_xor_sync(0xffffffffu, v, 1);
    return v;
}

// group-local barrier (4 warps, named barrier 1+q)
__device__ __forceinline__ void gsync(int q) {
    asm volatile("bar.sync %0, 128;" :: "r"(1 + q) : "memory");
}

// ---- acquire/release helpers ----
__device__ __forceinline__ void st_release(unsigned* p, unsigned v) {
    asm volatile("st.release.gpu.global.u32 [%0], %1;" :: "l"(p), "r"(v) : "memory");
}
__device__ __forceinline__ unsigned ld_acquire(unsigned* p) {
    unsigned v;
    asm volatile("ld.acquire.gpu.global.u32 %0, [%1];" : "=r"(v) : "l"(p) : "memory");
    return v;
}
__device__ __forceinline__ void red_release_add(unsigned* p, unsigned v) {
    asm volatile("red.release.gpu.global.add.u32 [%0], %1;" :: "l"(p), "r"(v) : "memory");
}
__device__ __forceinline__ unsigned atom_acqrel_add(unsigned* p, unsigned v) {
    unsigned old;
    asm volatile("atom.acq_rel.gpu.global.add.u32 %0, [%1], %2;"
                 : "=r"(old) : "l"(p), "r"(v) : "memory");
    return old;
}

// full grid barrier (NBLK blocks co-resident)
__device__ __forceinline__ void gbar() {
    __syncthreads();
    if (threadIdx.x == 0) {
        unsigned gen = ld_acquire(&g_gen);
        unsigned old = atom_acqrel_add(&g_cnt, 1u);
        if (old == NBLK - 1u) {
            asm volatile("st.relaxed.gpu.global.u32 [%0], %1;" :: "l"(&g_cnt), "r"(0u) : "memory");
            st_release(&g_gen, gen + 1u);
        } else {
            while (ld_acquire(&g_gen) == gen) {}
        }
    }
    __syncthreads();
}

// up-dot: cb0 = children base (incl +g*8); asr = thread's padded table row
__device__ __forceinline__ float dot_up(const float* __restrict__ cb0,
                                        const float* __restrict__ asr) {
    float sb = 0.f;
    #pragma unroll
    for (int l = 0; l < 4; l++) {
        const float4* bp = (const float4*)(cb0 + l*128);
        float4 x = bp[0], y = bp[1];
        const float* ar = asr + l*8;
        sb += ar[0]*x.x + ar[1]*x.y + ar[2]*x.z + ar[3]*x.w
            + ar[4]*y.x + ar[5]*y.y + ar[6]*y.z + ar[7]*y.w;
    }
    return sb;
}

// down-dot for one child row (row incl +g*8)
__device__ __forceinline__ void dot_dn(const float* __restrict__ row,
                                       const float* __restrict__ asr,
                                       const float* __restrict__ lar,
                                       int l, float& ce, float& ca) {
    const float4* bp = (const float4*)row;
    float4 x = bp[0], y = bp[1];
    const float* ar = asr + l*8;
    const float* lr = lar + l*8;
    ce = ar[0]*x.x + ar[1]*x.y + ar[2]*x.z + ar[3]*x.w
       + ar[4]*y.x + ar[5]*y.y + ar[6]*y.z + ar[7]*y.w;
    ca = lr[0]*x.x + lr[1]*x.y + lr[2]*x.z + lr[3]*x.w
       + lr[4]*y.x + lr[5]*y.y + lr[6]*y.z + lr[7]*y.w;
}

__global__ void __launch_bounds__(1024, 1)
main_kernel(const int* __restrict__ tn,
            const float* __restrict__ a,
            const float* __restrict__ b,
            const float* __restrict__ pi,
            const float* __restrict__ sp,
            float* __restrict__ out)
{
    extern __shared__ float sm[];
    const int tid = threadIdx.x, s = blockIdx.x;
    const int q = tid >> 7, wt = tid & 127, g = wt >> 3, i = wt & 7;
    int* slab = (int*)(sm + OFF_LAB);
    const float* asr = sm + OFF_ASP + wt*33;
    const float* lar = sm + OFF_ALA + wt*33;

    // ---- stage labels ----
    if (tid < 193) {
        int idx = tid, node;
        if      (idx < 128) node = 5461 + 128*s + idx;
        else if (idx < 160) node = 1365 + 32*s + (idx - 128);
        else if (idx < 168) node = 341 + 8*s + (idx - 160);
        else if (idx < 170) node = 85 + 2*s + (idx - 168);
        else if (idx == 170) node = (s < 64) ? (21 + s) : 21;
        else if (idx < 192) node = idx - 171;          // top nodes 0..20
        else                node = 21 + (s >> 1);      // own lvl3 ancestor
        slab[idx] = tn[node * 7];
    }
    // ---- reset flags ----
    if (tid == 0) {
        g_f1[s] = 0u;
        if (s == 0) g_c2 = 0u;
        if (s == 1) g_cfin = 0u;
    }

    // ================= phase 0a: softmax prep =================
    if (s < 16) {
        if (tid < 256) {
            int w = tid >> 5, ln = tid & 31;
            const float* bp = b + (s*8 + w) * 256;
            float mx = -1e30f;
            for (int m = ln; m < 256; m += 32) mx = fmaxf(mx, bp[m]);
            #pragma unroll
            for (int o = 16; o; o >>= 1) mx = fmaxf(mx, __shfl_xor_sync(0xffffffffu, mx, o));
            float ssum = 0.f;
            for (int m = ln; m < 256; m += 32) ssum += expf(bp[m] - mx);
            #pragma unroll
            for (int o = 16; o; o >>= 1) ssum += __shfl_xor_sync(0xffffffffu, ssum, o);
            float inv = 1.f / ssum, ls = logf(ssum);
            for (int m = ln; m < 256; m += 32) {
                float e = bp[m] - mx;
                g_bt [s*2048 + m*8 + w] = expf(e) * inv;
                g_lbt[s*2048 + m*8 + w] = e - ls;
            }
        }
    } else if (s == 16) {
        float* s_sp = sm + OFF_RED;   // 64 floats scratch
        if (tid < 16) {
            float v[4]; float mx = -1e30f;
            #pragma unroll
            for (int l = 0; l < 4; l++) { v[l] = sp[tid*4 + l]; mx = fmaxf(mx, v[l]); }
            float su = 0.f;
            #pragma unroll
            for (int l = 0; l < 4; l++) { v[l] = expf(v[l] - mx); su += v[l]; }
            float inv = 1.f / su;
            #pragma unroll
            for (int l = 0; l < 4; l++) {
                float smv = v[l] * inv;
                s_sp[tid*4 + l]  = smv;
                g_lsp[tid*4 + l] = logf(smv);
            }
        }
        if (tid < 64) {
            int gg = tid >> 2, l = tid & 3;
            float v[8]; float mx = -1e30f;
            #pragma unroll
            for (int c = 0; c < 8; c++) { v[c] = pi[gg*32 + c*4 + l]; mx = fmaxf(mx, v[c]); }
            float su = 0.f;
            #pragma unroll
            for (int c = 0; c < 8; c++) { v[c] = expf(v[c] - mx); su += v[c]; }
            float inv = 1.f / su, ls = logf(su);
            #pragma unroll
            for (int c = 0; c < 8; c++) {
                g_pit [gg*32 + l*8 + c] = v[c] * inv;
                g_lpit[gg*32 + l*8 + c] = logf(v[c]) - ls;
            }
        }
        __syncthreads();
        if (tid < 512) {   // sm_a: 512 (g,j,l) groups
            int gg = tid >> 5, j = (tid >> 2) & 7, l = tid & 3;
            float v[8]; float mx = -1e30f;
            #pragma unroll
            for (int ii = 0; ii < 8; ii++) {
                v[ii] = a[gg*256 + ii*32 + j*4 + l];
                mx = fmaxf(mx, v[ii]);
            }
            float su = 0.f;
            #pragma unroll
            for (int ii = 0; ii < 8; ii++) { v[ii] = expf(v[ii] - mx); su += v[ii]; }
            float inv = 1.f / su, ls = logf(su);
            float spv = s_sp[gg*4 + l];
            #pragma unroll
            for (int ii = 0; ii < 8; ii++) {
                int idx = ((gg*8 + ii)*4 + l)*8 + j;
                g_asp [idx] = v[ii] * inv * spv;
                g_loga[idx] = logf(v[ii]) - ls;
            }
        }
    } else if (s == 17) {
        if (tid < 16) g_accum[tid] = 0.f;
    }
    gbar();

    // ---- copy tables into padded smem (conflict-free layout) ----
    #pragma unroll
    for (int r = 0; r < 4; r++) {
        int idx = tid + r*1024;
        int row = idx >> 5, off = idx & 31;
        float av = g_asp[idx];
        float lv = g_loga[idx] * av;
        sm[OFF_ASP + row*33 + off] = av;
        sm[OFF_ALA + row*33 + off] = lv;
    }
    float lsp[4];
    #pragma unroll
    for (int l = 0; l < 4; l++) lsp[l] = g_lsp[g*4 + l];
    __syncthreads();

    // ================= phase 0b: leaf tables (1 row per group) =================
    {
        int t = s*8 + q;
        int l = t >> 8, lab = t & 255;
        float lb = g_pit[g*32 + l*8 + i] * g_bt[g*2048 + lab*8 + i];
        lb = __fdividef(lb, sum8(lb));
        float ce = 0.f, ca = 0.f;
        #pragma unroll
        for (int j = 0; j < 8; j++) {
            float v = __shfl_sync(0xffffffffu, lb, j, 8);
            ce += asr[l*8 + j] * v;
            ca += lar[l*8 + j] * v;
        }
        float w = lsp[l] + g_lpit[g*32 + l*8 + i] + g_lbt[g*2048 + lab*8 + i];
        g_uptab[t*128 + wt] = ce;
        g_dntab[t*128 + wt] = ca + w*ce;
    }
    gbar();

    // ================= phase 1: pair-of-subtrees up =================
    // lvl6 (32 nodes/block), BLOCKED: group q owns k = q*4 .. q*4+3
    float emis6[4];
    #pragma unroll
    for (int rr = 0; rr < 4; rr++)
        emis6[rr] = g_bt[g*2048 + slab[128 + q*4 + rr]*8 + i];
    #pragma unroll
    for (int rr = 0; rr < 4; rr++) {
        int k = q*4 + rr;
        int lab0 = slab[4*k], lab1 = slab[4*k+1], lab2 = slab[4*k+2], lab3 = slab[4*k+3];
        float sb = g_uptab[(0*256 + lab0)*128 + wt]
                 + g_uptab[(1*256 + lab1)*128 + wt]
                 + g_uptab[(2*256 + lab2)*128 + wt]
                 + g_uptab[(3*256 + lab3)*128 + wt];
        float tmp = emis6[rr] * sb;
        float ts = sum8(tmp);
        sm[OFF_B6 + k*128 + wt] = __fdividef(tmp, ts);
        sm[OFF_S6 + k*128 + wt] = sb;
    }
    gsync(q);   // group-local: lvl5 node q's children are this group's rows
    // lvl5 (8 nodes): group q owns node q
    {
        float sb = dot_up(sm + OFF_B6 + 4*q*128 + g*8, asr);
        float tmp = g_bt[g*2048 + slab[160 + q]*8 + i] * sb;
        float ts = sum8(tmp);
        sm[OFF_B5 + q*128 + wt] = __fdividef(tmp, ts);
        sm[OFF_S5 + q*128 + wt] = sb;
    }
    __syncthreads();   // lvl4 crosses groups
    // lvl4 (2 nodes, q<2)
    if (q < 2) {
        int t4 = 2*s + q;
        float sb = dot_up(sm + OFF_B5 + 4*q*128 + g*8, asr);
        float tmp = g_bt[g*2048 + slab[168 + q]*8 + i] * sb;
        float ts = sum8(tmp);
        g_beta4[t4*128 + wt] = __fdividef(tmp, ts);
        sm[OFF_S4 + q*128 + wt] = sb;
    }
    __syncthreads();
    if (tid == 0) st_release(&g_f1[s], 1u);

    // ================= lvl3 up (blocks 0..63) =================
    if (s < 64) {
        if (tid == 0) {
            while (ld_acquire(&g_f1[2*s])     == 0u) {}
            while (ld_acquire(&g_f1[2*s + 1]) == 0u) {}
        }
        __syncthreads();
        if (q == 0) {
            float sb = dot_up(&g_beta4[4*s*128 + g*8], asr);
            float tmp = g_bt[g*2048 + slab[170]*8 + i] * sb;
            float ts = sum8(tmp);
            g_beta3 [s*128 + wt] = __fdividef(tmp, ts);
            g_sbeta3[s*128 + wt] = sb;
        }
        __syncthreads();
        if (tid == 0) red_release_add(&g_c2, 1u);
    }

    // ================= wait all lvl3 ready =================
    if (tid == 0) {
        while (ld_acquire(&g_c2) != 64u) {}
    }
    __syncthreads();

    // copy all 64 beta3 rows to smem (2 float4 per thread)
    {
        float4* dst = (float4*)(sm + OFF_TOP);
        const float4* src = (const float4*)g_beta3;
        dst[tid]        = src[tid];
        dst[tid + 1024] = src[tid + 1024];
    }
    __syncthreads();

    // ================= redundant top: up lvl2/lvl1/root =================
    float acc = 0.f;
    #pragma unroll
    for (int rr = 0; rr < 2; rr++) {
        int k = rr*8 + q;
        float sb = dot_up(sm + OFF_TOP + 4*k*128 + g*8, asr);
        float tmp = g_bt[g*2048 + slab[176 + k]*8 + i] * sb;
        float ts = sum8(tmp);
        sm[OFF_B2 + k*128 + wt] = __fdividef(tmp, ts);
        sm[OFF_S2 + k*128 + wt] = sb;
    }
    __syncthreads();
    if (q < 4) {
        float sb = dot_up(sm + OFF_B2 + 4*q*128 + g*8, asr);
        float tmp = g_bt[g*2048 + slab[172 + q]*8 + i] * sb;
        float ts = sum8(tmp);
        sm[OFF_B1 + q*128 + wt] = __fdividef(tmp, ts);
        sm[OFF_S1 + q*128 + wt] = sb;
    }
    __syncthreads();
    // root up+down (group 0)
    if (q == 0) {
        float sb = dot_up(sm + OFF_B1 + g*8, asr);
        int lab0 = slab[171];
        float tmp = g_bt[g*2048 + lab0*8 + i] * sb;
        float ts = sum8(tmp);
        float betar = __fdividef(tmp, ts);
        float pe = __fdividef(betar, sb);
        if (s == 0) acc += betar * g_lbt[g*2048 + lab0*8 + i];
        #pragma unroll
        for (int l = 0; l < 4; l++) {
            float ce, ca;
            dot_dn(sm + OFF_B1 + l*128 + g*8, asr, lar, l, ce, ca);
            ce *= pe;
            sm[OFF_E1 + l*128 + wt] = ce;
            if (s == 0) acc += pe*ca + lsp[l]*ce;
        }
    }
    __syncthreads();
    // down lvl1 (groups 0..3 = nodes 0..3)
    if (q < 4) {
        float epsv = sm[OFF_E1 + q*128 + wt];
        float pe = __fdividef(epsv, sm[OFF_S1 + q*128 + wt]);
        if (s == 0) acc += epsv * g_lbt[g*2048 + slab[172 + q]*8 + i];
        #pragma unroll
        for (int l = 0; l < 4; l++) {
            float ce, ca;
            dot_dn(sm + OFF_B2 + (4*q + l)*128 + g*8, asr, lar, l, ce, ca);
            ce *= pe;
            sm[OFF_E2 + (4*q + l)*128 + wt] = ce;
            if (s == 0) acc += pe*ca + lsp[l]*ce;
        }
    }
    __syncthreads();
    // down lvl2: block0 full (acc); others own node only
    if (s == 0) {
        #pragma unroll
        for (int rr = 0; rr < 2; rr++) {
            int k = rr*8 + q;
            float epsv = sm[OFF_E2 + k*128 + wt];
            float pe = __fdividef(epsv, sm[OFF_S2 + k*128 + wt]);
            acc += epsv * g_lbt[g*2048 + slab[176 + k]*8 + i];
            #pragma unroll
            for (int l = 0; l < 4; l++) {
                float ce, ca;
                dot_dn(sm + OFF_TOP + (4*k + l)*128 + g*8, asr, lar, l, ce, ca);
                ce *= pe;
                acc += pe*ca + lsp[l]*ce;
                if (4*k + l == 0) sm[OFF_E3 + wt] = ce;
            }
        }
    } else if (q == 0) {
        int t = s >> 1, p2 = t >> 2, lc = t & 3;
        float epsv = sm[OFF_E2 + p2*128 + wt];
        float pe = __fdividef(epsv, sm[OFF_S2 + p2*128 + wt]);
        const float4* bp = (const float4*)(sm + OFF_TOP + (4*p2 + lc)*128 + g*8);
        float4 x = bp[0], y = bp[1];
        const float* ar = asr + lc*8;
        float ce = ar[0]*x.x + ar[1]*x.y + ar[2]*x.z + ar[3]*x.w
                 + ar[4]*y.x + ar[5]*y.y + ar[6]*y.z + ar[7]*y.w;
        sm[OFF_E3 + wt] = ce * pe;
    }
    // lvl3 down (group 0)
    if (q == 0) {
        int t = s >> 1;
        int half = s & 1;
        float eps3 = sm[OFF_E3 + wt];
        float pe3 = __fdividef(eps3, g_sbeta3[t*128 + wt]);
        if (half == 0) acc += eps3 * g_lbt[g*2048 + slab[192]*8 + i];
        #pragma unroll
        for (int l = 0; l < 4; l++) {
            float ce, ca;
            dot_dn(&g_beta4[(4*t + l)*128 + g*8], asr, lar, l, ce, ca);
            ce *= pe3;
            int lown = l - 2*half;
            if (lown == 0 || lown == 1) {
                acc += pe3*ca + lsp[l]*ce;
                sm[OFF_E4 + lown*128 + wt] = ce;
            }
        }
    }
    __syncthreads();

    // ================= phase 3: pair-of-subtrees down =================
    if (q < 2) {
        float epsv = sm[OFF_E4 + q*128 + wt];
        float pe = __fdividef(epsv, sm[OFF_S4 + q*128 + wt]);
        acc += epsv * g_lbt[g*2048 + slab[168 + q]*8 + i];
        #pragma unroll
        for (int l = 0; l < 4; l++) {
            float ce, ca;
            dot_dn(sm + OFF_B5 + (4*q + l)*128 + g*8, asr, lar, l, ce, ca);
            ce *= pe;
            sm[OFF_E5 + (4*q + l)*128 + wt] = ce;
            acc += pe*ca + lsp[l]*ce;
        }
    }
    __syncthreads();   // E5 crosses groups
    // lvl5 down: group q owns node q
    {
        float epsv = sm[OFF_E5 + q*128 + wt];
        float pe = __fdividef(epsv, sm[OFF_S5 + q*128 + wt]);
        acc += epsv * g_lbt[g*2048 + slab[160 + q]*8 + i];
        #pragma unroll
        for (int l = 0; l < 4; l++) {
            float ce, ca;
            dot_dn(sm + OFF_B6 + (4*q + l)*128 + g*8, asr, lar, l, ce, ca);
            ce *= pe;
            sm[OFF_E6 + (4*q + l)*128 + wt] = ce;
            acc += pe*ca + lsp[l]*ce;
        }
    }
    gsync(q);   // group-local: lvl6 nodes q*4.. consume only this group's rows
    // lvl6 down (4 iters, BLOCKED): leaf children via dn_tab
    float lemis6[4];
    #pragma unroll
    for (int rr = 0; rr < 4; rr++)
        lemis6[rr] = g_lbt[g*2048 + slab[128 + q*4 + rr]*8 + i];
    #pragma unroll
    for (int rr = 0; rr < 4; rr++) {
        int k = q*4 + rr;
        int lab0 = slab[4*k], lab1 = slab[4*k+1], lab2 = slab[4*k+2], lab3 = slab[4*k+3];
        float epsv = sm[OFF_E6 + k*128 + wt];
        float pe = __fdividef(epsv, sm[OFF_S6 + k*128 + wt]);
        acc += epsv * lemis6[rr];
        float d = g_dntab[(0*256 + lab0)*128 + wt]
                + g_dntab[(1*256 + lab1)*128 + wt]
                + g_dntab[(2*256 + lab2)*128 + wt]
                + g_dntab[(3*256 + lab3)*128 + wt];
        acc += pe * d;
    }

    // ================= reduce + finish ticket =================
    acc = sum8(acc);
    if (i == 0) sm[OFF_RED + q*16 + g] = acc;
    __syncthreads();
    if (tid < 16) {
        float p = 0.f;
        #pragma unroll
        for (int k = 0; k < 8; k++) p += sm[OFF_RED + k*16 + tid];
        atomicAdd(&g_accum[tid], p);
    }
    __syncthreads();
    unsigned* plast = (unsigned*)(sm + OFF_LAST);
    if (tid == 0) {
        unsigned old = atom_acqrel_add(&g_cfin, 1u);
        *plast = (old == NBLK - 1u) ? 1u : 0u;
    }
    __syncthreads();
    if (*plast && tid < 16)
        out[tid] = *(volatile float*)&g_accum[tid];
}

// ---------------------------------------------------------------------------
extern "C" void kernel_launch(void* const* d_in, const int* in_sizes, int n_in,
                              void* d_out, int out_size)
{
    const int*   tn = (const int*)  d_in[0];
    const float* a  = (const float*)d_in[2];
    const float* b  = (const float*)d_in[3];
    const float* pi = (const float*)d_in[4];
    const float* sp = (const float*)d_in[5];
    float* out = (float*)d_out;

    cudaFuncSetAttribute(main_kernel,
                         cudaFuncAttributeMaxDynamicSharedMemorySize,
                         SMEM_FLOATS * 4);
    main_kernel<<<NBLK, 1024, SMEM_FLOATS * 4>>>(tn, a, b, pi, sp, out);
}

// round 13
// speedup vs baseline: 2.2482x; 1.1405x over previous
#include <cuda_runtime.h>

// ---------------------------------------------------------------------------
// BottomUpHTMM — complete 4-ary tree depth 7, single persistent kernel.
// 128 blocks x 1024 threads (8 groups of 128 = (g,c)); each block owns two
// level-4 subtrees. a_sp / a_sp*log(a) tables in PADDED shared memory
// (stride 33 -> conflict-free LDS) => regs<=64 => 32 warps/SM.
// b-softmax distributed one row per block. Top serial steps group-split.
// ---------------------------------------------------------------------------

#define GC    128
#define NBLK  128

// tables (global)
__device__ float g_asp [4096];      // a_sp[g][i][l][j]   (wt=g*8+i -> wt*32+l*8+j)
__device__ float g_loga[4096];      // log sm_a
__device__ float g_bt  [16*256*8];  // sm_b[g][m][c]
__device__ float g_lbt [16*256*8];
__device__ float g_pit [512];       // sm_pi[g][pos][c]
__device__ float g_lpit[512];
__device__ float g_lsp [64];        // log sm_sp[g][l]

// leaf contribution tables: index (l*256+lab)*128 + wt
__device__ float g_uptab[1024 * GC];
__device__ float g_dntab[1024 * GC];

// cross-block state
__device__ float g_beta4 [256 * GC];
__device__ float g_beta3 [64 * GC];
__device__ float g_sbeta3[64 * GC];
__device__ float g_accum [16];

// sync state
__device__ unsigned g_cnt = 0;
__device__ unsigned g_gen = 0;
__device__ unsigned g_f1[NBLK];     // beta4 pair of block s ready
__device__ unsigned g_c2;           // # lvl3 nodes done
__device__ unsigned g_cfin;         // finish ticket

// shared-memory layout (floats)
#define OFF_ASP   0        // 128 rows x 33 (padded, conflict-free)
#define OFF_ALA   4224     // 128 rows x 33
#define OFF_B6    8448     // 32 rows x 128
#define OFF_S6    12544    // 32 rows
#define OFF_B5    16640    // 8 rows
#define OFF_S5    17664    // 8 rows
#define OFF_S4    18688    // 2 rows
#define OFF_E5    18944    // 8 rows
#define OFF_E6    19968    // 32 rows
#define OFF_TOP   24064    // 64 rows beta3 copy
#define OFF_B2    32256    // 16 rows
#define OFF_S2    34304    // 16 rows
#define OFF_B1    36352    // 4 rows
#define OFF_S1    36864    // 4 rows
#define OFF_E1    37376    // 4 rows
#define OFF_E2    37888    // 16 rows
#define OFF_E3    39936    // 1 row
#define OFF_E4    40064    // 2 rows
#define OFF_RED   40320    // 128 (b-reduce scratch 0..15, s_sp at +32)
#define OFF_LAB   40448    // 208 ints
#define OFF_LAST  40656    // 1
#define SMEM_FLOATS 40660  // ~158.8 KB

__device__ __forceinline__ float sum8(float v) {
    v += __shfl_xor_sync(0xffffffffu, v, 4);
    v += __shfl_xor_sync(0xffffffffu, v, 2);
    v += __shfl_xor_sync(0xffffffffu, v, 1);
    return v;
}

// group-local barrier (4 warps, named barrier 1+q)
__device__ __forceinline__ void gsync(int q) {
    asm volatile("bar.sync %0, 128;" :: "r"(1 + q) : "memory");
}

// ---- acquire/release helpers ----
__device__ __forceinline__ void st_release(unsigned* p, unsigned v) {
    asm volatile("st.release.gpu.global.u32 [%0], %1;" :: "l"(p), "r"(v) : "memory");
}
__device__ __forceinline__ unsigned ld_acquire(unsigned* p) {
    unsigned v;
    asm volatile("ld.acquire.gpu.global.u32 %0, [%1];" : "=r"(v) : "l"(p) : "memory");
    return v;
}
__device__ __forceinline__ void red_release_add(unsigned* p, unsigned v) {
    asm volatile("red.release.gpu.global.add.u32 [%0], %1;" :: "l"(p), "r"(v) : "memory");
}
__device__ __forceinline__ unsigned atom_acqrel_add(unsigned* p, unsigned v) {
    unsigned old;
    asm volatile("atom.acq_rel.gpu.global.add.u32 %0, [%1], %2;"
                 : "=r"(old) : "l"(p), "r"(v) : "memory");
    return old;
}

// full grid barrier (NBLK blocks co-resident)
__device__ __forceinline__ void gbar() {
    __syncthreads();
    if (threadIdx.x == 0) {
        unsigned gen = ld_acquire(&g_gen);
        unsigned old = atom_acqrel_add(&g_cnt, 1u);
        if (old == NBLK - 1u) {
            asm volatile("st.relaxed.gpu.global.u32 [%0], %1;" :: "l"(&g_cnt), "r"(0u) : "memory");
            st_release(&g_gen, gen + 1u);
        } else {
            while (ld_acquire(&g_gen) == gen) {}
        }
    }
    __syncthreads();
}

// up-dot: cb0 = children base (incl +g*8); asr = thread's padded table row
__device__ __forceinline__ float dot_up(const float* __restrict__ cb0,
                                        const float* __restrict__ asr) {
    float sb = 0.f;
    #pragma unroll
    for (int l = 0; l < 4; l++) {
        const float4* bp = (const float4*)(cb0 + l*128);
        float4 x = bp[0], y = bp[1];
        const float* ar = asr + l*8;
        sb += ar[0]*x.x + ar[1]*x.y + ar[2]*x.z + ar[3]*x.w
            + ar[4]*y.x + ar[5]*y.y + ar[6]*y.z + ar[7]*y.w;
    }
    return sb;
}

// down-dot for one child row (row incl +g*8)
__device__ __forceinline__ void dot_dn(const float* __restrict__ row,
                                       const float* __restrict__ asr,
                                       const float* __restrict__ lar,
                                       int l, float& ce, float& ca) {
    const float4* bp = (const float4*)row;
    float4 x = bp[0], y = bp[1];
    const float* ar = asr + l*8;
    const float* lr = lar + l*8;
    ce = ar[0]*x.x + ar[1]*x.y + ar[2]*x.z + ar[3]*x.w
       + ar[4]*y.x + ar[5]*y.y + ar[6]*y.z + ar[7]*y.w;
    ca = lr[0]*x.x + lr[1]*x.y + lr[2]*x.z + lr[3]*x.w
       + lr[4]*y.x + lr[5]*y.y + lr[6]*y.z + lr[7]*y.w;
}

__global__ void __launch_bounds__(1024, 1)
main_kernel(const int* __restrict__ tn,
            const float* __restrict__ a,
            const float* __restrict__ b,
            const float* __restrict__ pi,
            const float* __restrict__ sp,
            float* __restrict__ out)
{
    extern __shared__ float sm[];
    const int tid = threadIdx.x, s = blockIdx.x;
    const int q = tid >> 7, wt = tid & 127, g = wt >> 3, i = wt & 7;
    int* slab = (int*)(sm + OFF_LAB);
    const float* asr = sm + OFF_ASP + wt*33;
    const float* lar = sm + OFF_ALA + wt*33;

    // ---- stage labels ----
    if (tid < 193) {
        int idx = tid, node;
        if      (idx < 128) node = 5461 + 128*s + idx;
        else if (idx < 160) node = 1365 + 32*s + (idx - 128);
        else if (idx < 168) node = 341 + 8*s + (idx - 160);
        else if (idx < 170) node = 85 + 2*s + (idx - 168);
        else if (idx == 170) node = (s < 64) ? (21 + s) : 21;
        else if (idx < 192) node = idx - 171;          // top nodes 0..20
        else                node = 21 + (s >> 1);      // own lvl3 ancestor
        slab[idx] = tn[node * 7];
    }
    // ---- reset flags ----
    if (tid == 0) {
        g_f1[s] = 0u;
        if (s == 0) g_c2 = 0u;
        if (s == 1) g_cfin = 0u;
    }
    if (s == 17 && tid >= 512 && tid < 528) g_accum[tid - 512] = 0.f;

    // ================= phase 0a: distributed softmax prep =================
    // every block: one b-row (g = s>>3, c = s&7), 256 threads, 1 elem/thread
    float bv = 0.f, be = 0.f, bls = 0.f;
    {
        const int gB = s >> 3, wB = s & 7;
        if (tid < 256) {
            bv = b[s*256 + tid];
            float mx = bv;
            #pragma unroll
            for (int o = 16; o; o >>= 1) mx = fmaxf(mx, __shfl_xor_sync(0xffffffffu, mx, o));
            if ((tid & 31) == 0) sm[OFF_RED + (tid >> 5)] = mx;
        }
        // block 127 extras: sp (16 thr), pi (64 thr)
        if (s == 127) {
            if (tid >= 256 && tid < 272) {
                int t16 = tid - 256;
                float v[4]; float mx = -1e30f;
                #pragma unroll
                for (int l = 0; l < 4; l++) { v[l] = sp[t16*4 + l]; mx = fmaxf(mx, v[l]); }
                float su = 0.f;
                #pragma unroll
                for (int l = 0; l < 4; l++) { v[l] = expf(v[l] - mx); su += v[l]; }
                float inv = 1.f / su;
                #pragma unroll
                for (int l = 0; l < 4; l++) {
                    float smv = v[l] * inv;
                    sm[OFF_RED + 32 + t16*4 + l] = smv;     // s_sp
                    g_lsp[t16*4 + l] = logf(smv);
                }
            }
            if (tid >= 320 && tid < 384) {
                int t2 = tid - 320;
                int gg = t2 >> 2, l = t2 & 3;
                float v[8]; float mx = -1e30f;
                #pragma unroll
                for (int c = 0; c < 8; c++) { v[c] = pi[gg*32 + c*4 + l]; mx = fmaxf(mx, v[c]); }
                float su = 0.f;
                #pragma unroll
                for (int c = 0; c < 8; c++) { v[c] = expf(v[c] - mx); su += v[c]; }
                float inv = 1.f / su, ls = logf(su);
                #pragma unroll
                for (int c = 0; c < 8; c++) {
                    g_pit [gg*32 + l*8 + c] = v[c] * inv;
                    g_lpit[gg*32 + l*8 + c] = logf(v[c]) - ls;
                }
            }
        }
        __syncthreads();
        if (tid < 256) {
            float m8 = sm[OFF_RED];
            #pragma unroll
            for (int k = 1; k < 8; k++) m8 = fmaxf(m8, sm[OFF_RED + k]);
            bv -= m8;
            be = expf(bv);
            float su = be;
            #pragma unroll
            for (int o = 16; o; o >>= 1) su += __shfl_xor_sync(0xffffffffu, su, o);
            if ((tid & 31) == 0) sm[OFF_RED + 8 + (tid >> 5)] = su;
        }
        // block 127: a-softmax on threads 512..1023 (s_sp ready after sync above)
        if (s == 127 && tid >= 512) {
            int grp = tid - 512;
            int gg = grp >> 5, j = (grp >> 2) & 7, l = grp & 3;
            float v[8]; float mx = -1e30f;
            #pragma unroll
            for (int ii = 0; ii < 8; ii++) {
                v[ii] = a[gg*256 + ii*32 + j*4 + l];
                mx = fmaxf(mx, v[ii]);
            }
            float su = 0.f;
            #pragma unroll
            for (int ii = 0; ii < 8; ii++) { v[ii] = expf(v[ii] - mx); su += v[ii]; }
            float inv = 1.f / su, ls = logf(su);
            float spv = sm[OFF_RED + 32 + gg*4 + l];
            #pragma unroll
            for (int ii = 0; ii < 8; ii++) {
                int idx = ((gg*8 + ii)*4 + l)*8 + j;
                g_asp [idx] = v[ii] * inv * spv;
                g_loga[idx] = logf(v[ii]) - ls;
            }
        }
        __syncthreads();
        if (tid < 256) {
            float s8 = 0.f;
            #pragma unroll
            for (int k = 0; k < 8; k++) s8 += sm[OFF_RED + 8 + k];
            float inv = 1.f / s8;
            bls = logf(s8);
            g_bt [gB*2048 + tid*8 + wB] = be * inv;
            g_lbt[gB*2048 + tid*8 + wB] = bv - bls;
        }
    }
    gbar();

    // ---- copy tables into padded smem (conflict-free layout) ----
    #pragma unroll
    for (int r = 0; r < 4; r++) {
        int idx = tid + r*1024;
        int row = idx >> 5, off = idx & 31;
        float av = g_asp[idx];
        float lv = g_loga[idx] * av;
        sm[OFF_ASP + row*33 + off] = av;
        sm[OFF_ALA + row*33 + off] = lv;
    }
    float lsp[4];
    #pragma unroll
    for (int l = 0; l < 4; l++) lsp[l] = g_lsp[g*4 + l];
    __syncthreads();

    // ================= phase 0b: leaf tables (1 row per group) =================
    {
        int t = s*8 + q;
        int l = t >> 8, lab = t & 255;
        float lb = g_pit[g*32 + l*8 + i] * g_bt[g*2048 + lab*8 + i];
        lb = __fdividef(lb, sum8(lb));
        float ce = 0.f, ca = 0.f;
        #pragma unroll
        for (int j = 0; j < 8; j++) {
            float v = __shfl_sync(0xffffffffu, lb, j, 8);
            ce += asr[l*8 + j] * v;
            ca += lar[l*8 + j] * v;
        }
        float w = lsp[l] + g_lpit[g*32 + l*8 + i] + g_lbt[g*2048 + lab*8 + i];
        g_uptab[t*128 + wt] = ce;
        g_dntab[t*128 + wt] = ca + w*ce;
    }
    gbar();

    // ================= phase 1: pair-of-subtrees up =================
    // lvl6 (32 nodes/block), BLOCKED: group q owns k = q*4 .. q*4+3
    float emis6[4];
    #pragma unroll
    for (int rr = 0; rr < 4; rr++)
        emis6[rr] = g_bt[g*2048 + slab[128 + q*4 + rr]*8 + i];
    #pragma unroll
    for (int rr = 0; rr < 4; rr++) {
        int k = q*4 + rr;
        int lab0 = slab[4*k], lab1 = slab[4*k+1], lab2 = slab[4*k+2], lab3 = slab[4*k+3];
        float sb = g_uptab[(0*256 + lab0)*128 + wt]
                 + g_uptab[(1*256 + lab1)*128 + wt]
                 + g_uptab[(2*256 + lab2)*128 + wt]
                 + g_uptab[(3*256 + lab3)*128 + wt];
        float tmp = emis6[rr] * sb;
        float ts = sum8(tmp);
        sm[OFF_B6 + k*128 + wt] = __fdividef(tmp, ts);
        sm[OFF_S6 + k*128 + wt] = sb;
    }
    gsync(q);   // group-local: lvl5 node q's children are this group's rows
    // lvl5 (8 nodes): group q owns node q
    {
        float sb = dot_up(sm + OFF_B6 + 4*q*128 + g*8, asr);
        float tmp = g_bt[g*2048 + slab[160 + q]*8 + i] * sb;
        float ts = sum8(tmp);
        sm[OFF_B5 + q*128 + wt] = __fdividef(tmp, ts);
        sm[OFF_S5 + q*128 + wt] = sb;
    }
    __syncthreads();   // lvl4 crosses groups
    // lvl4 (2 nodes, q<2)
    if (q < 2) {
        int t4 = 2*s + q;
        float sb = dot_up(sm + OFF_B5 + 4*q*128 + g*8, asr);
        float tmp = g_bt[g*2048 + slab[168 + q]*8 + i] * sb;
        float ts = sum8(tmp);
        g_beta4[t4*128 + wt] = __fdividef(tmp, ts);
        sm[OFF_S4 + q*128 + wt] = sb;
    }
    __syncthreads();
    if (tid == 0) st_release(&g_f1[s], 1u);

    // ================= lvl3 up (blocks 0..63) =================
    if (s < 64) {
        if (tid == 0) {
            while (ld_acquire(&g_f1[2*s])     == 0u) {}
            while (ld_acquire(&g_f1[2*s + 1]) == 0u) {}
        }
        __syncthreads();
        if (q == 0) {
            float sb = dot_up(&g_beta4[4*s*128 + g*8], asr);
            float tmp = g_bt[g*2048 + slab[170]*8 + i] * sb;
            float ts = sum8(tmp);
            g_beta3 [s*128 + wt] = __fdividef(tmp, ts);
            g_sbeta3[s*128 + wt] = sb;
        }
        __syncthreads();
        if (tid == 0) red_release_add(&g_c2, 1u);
    }

    // ================= wait all lvl3 ready =================
    if (tid == 0) {
        while (ld_acquire(&g_c2) != 64u) {}
    }
    __syncthreads();

    // copy all 64 beta3 rows to smem (2 float4 per thread)
    {
        float4* dst = (float4*)(sm + OFF_TOP);
        const float4* src = (const float4*)g_beta3;
        dst[tid]        = src[tid];
        dst[tid + 1024] = src[tid + 1024];
    }
    __syncthreads();

    // ================= redundant top: up lvl2/lvl1/root =================
    float acc = 0.f;
    #pragma unroll
    for (int rr = 0; rr < 2; rr++) {
        int k = rr*8 + q;
        float sb = dot_up(sm + OFF_TOP + 4*k*128 + g*8, asr);
        float tmp = g_bt[g*2048 + slab[176 + k]*8 + i] * sb;
        float ts = sum8(tmp);
        sm[OFF_B2 + k*128 + wt] = __fdividef(tmp, ts);
        sm[OFF_S2 + k*128 + wt] = sb;
    }
    __syncthreads();
    if (q < 4) {
        float sb = dot_up(sm + OFF_B2 + 4*q*128 + g*8, asr);
        float tmp = g_bt[g*2048 + slab[172 + q]*8 + i] * sb;
        float ts = sum8(tmp);
        sm[OFF_B1 + q*128 + wt] = __fdividef(tmp, ts);
        sm[OFF_S1 + q*128 + wt] = sb;
    }
    __syncthreads();
    // root up+down: groups 0..3 (betar redundant; child l = q each)
    if (q < 4) {
        float sb = dot_up(sm + OFF_B1 + g*8, asr);
        int lab0 = slab[171];
        float tmp = g_bt[g*2048 + lab0*8 + i] * sb;
        float ts = sum8(tmp);
        float betar = __fdividef(tmp, ts);
        float pe = __fdividef(betar, sb);
        if (s == 0 && q == 0) acc += betar * g_lbt[g*2048 + lab0*8 + i];
        int l = q;
        float ce, ca;
        dot_dn(sm + OFF_B1 + l*128 + g*8, asr, lar, l, ce, ca);
        ce *= pe;
        sm[OFF_E1 + l*128 + wt] = ce;
        if (s == 0) acc += pe*ca + lsp[l]*ce;
    }
    __syncthreads();
    // down lvl1: all 8 groups; node n=q>>1, children 2h, 2h+1
    {
        int n = q >> 1, h = q & 1;
        float epsv = sm[OFF_E1 + n*128 + wt];
        float pe = __fdividef(epsv, sm[OFF_S1 + n*128 + wt]);
        if (s == 0 && h == 0) acc += epsv * g_lbt[g*2048 + slab[172 + n]*8 + i];
        #pragma unroll
        for (int dl = 0; dl < 2; dl++) {
            int l = 2*h + dl;
            float ce, ca;
            dot_dn(sm + OFF_B2 + (4*n + l)*128 + g*8, asr, lar, l, ce, ca);
            ce *= pe;
            sm[OFF_E2 + (4*n + l)*128 + wt] = ce;
            if (s == 0) acc += pe*ca + lsp[l]*ce;
        }
    }
    __syncthreads();
    // down lvl2: block0 full (acc); others own node only
    if (s == 0) {
        #pragma unroll
        for (int rr = 0; rr < 2; rr++) {
            int k = rr*8 + q;
            float epsv = sm[OFF_E2 + k*128 + wt];
            float pe = __fdividef(epsv, sm[OFF_S2 + k*128 + wt]);
            acc += epsv * g_lbt[g*2048 + slab[176 + k]*8 + i];
            #pragma unroll
            for (int l = 0; l < 4; l++) {
                float ce, ca;
                dot_dn(sm + OFF_TOP + (4*k + l)*128 + g*8, asr, lar, l, ce, ca);
                ce *= pe;
                acc += pe*ca + lsp[l]*ce;
                if (4*k + l == 0) sm[OFF_E3 + wt] = ce;
            }
        }
    } else if (q == 0) {
        int t = s >> 1, p2 = t >> 2, lc = t & 3;
        float epsv = sm[OFF_E2 + p2*128 + wt];
        float pe = __fdividef(epsv, sm[OFF_S2 + p2*128 + wt]);
        const float4* bp = (const float4*)(sm + OFF_TOP + (4*p2 + lc)*128 + g*8);
        float4 x = bp[0], y = bp[1];
        const float* ar = asr + lc*8;
        float ce = ar[0]*x.x + ar[1]*x.y + ar[2]*x.z + ar[3]*x.w
                 + ar[4]*y.x + ar[5]*y.y + ar[6]*y.z + ar[7]*y.w;
        sm[OFF_E3 + wt] = ce * pe;
    }
    // lvl3 down (group 0)
    if (q == 0) {
        int t = s >> 1;
        int half = s & 1;
        float eps3 = sm[OFF_E3 + wt];
        float pe3 = __fdividef(eps3, g_sbeta3[t*128 + wt]);
        if (half == 0) acc += eps3 * g_lbt[g*2048 + slab[192]*8 + i];
        #pragma unroll
        for (int l = 0; l < 4; l++) {
            float ce, ca;
            dot_dn(&g_beta4[(4*t + l)*128 + g*8], asr, lar, l, ce, ca);
            ce *= pe3;
            int lown = l - 2*half;
            if (lown == 0 || lown == 1) {
                acc += pe3*ca + lsp[l]*ce;
                sm[OFF_E4 + lown*128 + wt] = ce;
            }
        }
    }
    __syncthreads();

    // ================= phase 3: pair-of-subtrees down =================
    // lvl4 down: groups 0..3; node n=q>>1, children 2h, 2h+1
    if (q < 4) {
        int n = q >> 1, h = q & 1;
        float epsv = sm[OFF_E4 + n*128 + wt];
        float pe = __fdividef(epsv, sm[OFF_S4 + n*128 + wt]);
        if (h == 0) acc += epsv * g_lbt[g*2048 + slab[168 + n]*8 + i];
        #pragma unroll
        for (int dl = 0; dl < 2; dl++) {
            int l = 2*h + dl;
            float ce, ca;
            dot_dn(sm + OFF_B5 + (4*n + l)*128 + g*8, asr, lar, l, ce, ca);
            ce *= pe;
            sm[OFF_E5 + (4*n + l)*128 + wt] = ce;
            acc += pe*ca + lsp[l]*ce;
        }
    }
    __syncthreads();   // E5 crosses groups
    // lvl5 down: group q owns node q
    {
        float epsv = sm[OFF_E5 + q*128 + wt];
        float pe = __fdividef(epsv, sm[OFF_S5 + q*128 + wt]);
        acc += epsv * g_lbt[g*2048 + slab[160 + q]*8 + i];
        #pragma unroll
        for (int l = 0; l < 4; l++) {
            float ce, ca;
            dot_dn(sm + OFF_B6 + (4*q + l)*128 + g*8, asr, lar, l, ce, ca);
            ce *= pe;
            sm[OFF_E6 + (4*q + l)*128 + wt] = ce;
            acc += pe*ca + lsp[l]*ce;
        }
    }
    gsync(q);   // group-local: lvl6 nodes q*4.. consume only this group's rows
    // lvl6 down (4 iters, BLOCKED): leaf children via dn_tab
    float lemis6[4];
    #pragma unroll
    for (int rr = 0; rr < 4; rr++)
        lemis6[rr] = g_lbt[g*2048 + slab[128 + q*4 + rr]*8 + i];
    #pragma unroll
    for (int rr = 0; rr < 4; rr++) {
        int k = q*4 + rr;
        int lab0 = slab[4*k], lab1 = slab[4*k+1], lab2 = slab[4*k+2], lab3 = slab[4*k+3];
        float epsv = sm[OFF_E6 + k*128 + wt];
        float pe = __fdividef(epsv, sm[OFF_S6 + k*128 + wt]);
        acc += epsv * lemis6[rr];
        float d = g_dntab[(0*256 + lab0)*128 + wt]
                + g_dntab[(1*256 + lab1)*128 + wt]
                + g_dntab[(2*256 + lab2)*128 + wt]
                + g_dntab[(3*256 + lab3)*128 + wt];
        acc += pe * d;
    }

    // ================= reduce + finish ticket =================
    acc = sum8(acc);
    if (i == 0) sm[OFF_RED + q*16 + g] = acc;
    __syncthreads();
    if (tid < 16) {
        float p = 0.f;
        #pragma unroll
        for (int k = 0; k < 8; k++) p += sm[OFF_RED + k*16 + tid];
        atomicAdd(&g_accum[tid], p);
    }
    __syncthreads();
    unsigned* plast = (unsigned*)(sm + OFF_LAST);
    if (tid == 0) {
        unsigned old = atom_acqrel_add(&g_cfin, 1u);
        *plast = (old == NBLK - 1u) ? 1u : 0u;
    }
    __syncthreads();
    if (*plast && tid < 16)
        out[tid] = *(volatile float*)&g_accum[tid];
}

// ---------------------------------------------------------------------------
extern "C" void kernel_launch(void* const* d_in, const int* in_sizes, int n_in,
                              void* d_out, int out_size)
{
    const int*   tn = (const int*)  d_in[0];
    const float* a  = (const float*)d_in[2];
    const float* b  = (const float*)d_in[3];
    const float* pi = (const float*)d_in[4];
    const float* sp = (const float*)d_in[5];
    float* out = (float*)d_out;

    cudaFuncSetAttribute(main_kernel,
                         cudaFuncAttributeMaxDynamicSharedMemorySize,
                         SMEM_FLOATS * 4);
    main_kernel<<<NBLK, 1024, SMEM_FLOATS * 4>>>(tn, a, b, pi, sp, out);
}